// round 1
// baseline (speedup 1.0000x reference)
#include <cuda_runtime.h>
#include <math.h>

#define DIM 1536
#define NH 12
#define HD 128
#define CPAIR 64
#define MAXL 2400
#define EPS 1e-6f
#define ATT_SCALE 0.08838834764831843f   // 1/sqrt(128)

// ---------------- scratch (device globals; no allocation allowed) ----------
__device__ float g_q[MAXL * DIM];
__device__ float g_k[MAXL * DIM];
__device__ float g_v[MAXL * DIM];
__device__ float g_a[MAXL * DIM];

// ---------------------------------------------------------------------------
// SGEMM: C[M,N] = A[M,K] @ B[N,K]^T + bias[N]
// 128x128 tile, BK=16, 256 threads, 8x8 per thread.
// ---------------------------------------------------------------------------
#define BM 128
#define BN 128
#define BK 16

__global__ __launch_bounds__(256, 2)
void gemm_bias_kernel(const float* __restrict__ A, const float* __restrict__ B,
                      const float* __restrict__ bias, float* __restrict__ Cmat,
                      int M, int N, int K) {
    __shared__ float As[BK][BM];
    __shared__ float Bs[BK][BN];

    const int tid = threadIdx.x;
    const int bm = blockIdx.y * BM;
    const int bn = blockIdx.x * BN;
    const int tx = tid & 15;        // 0..15 -> col group
    const int ty = tid >> 4;        // 0..15 -> row group

    float acc[8][8];
#pragma unroll
    for (int i = 0; i < 8; i++)
#pragma unroll
        for (int j = 0; j < 8; j++) acc[i][j] = 0.f;

    for (int kt = 0; kt < K; kt += BK) {
#pragma unroll
        for (int i = 0; i < 2; i++) {
            int f = tid + i * 256;          // 0..511 float4 slots
            int row = f >> 2;               // 0..127
            int c4  = (f & 3) * 4;          // 0,4,8,12
            float4 av;
            if (bm + row < M)
                av = *(const float4*)&A[(size_t)(bm + row) * K + kt + c4];
            else
                av = make_float4(0.f, 0.f, 0.f, 0.f);
            As[c4 + 0][row] = av.x; As[c4 + 1][row] = av.y;
            As[c4 + 2][row] = av.z; As[c4 + 3][row] = av.w;
            float4 bv = *(const float4*)&B[(size_t)(bn + row) * K + kt + c4];
            Bs[c4 + 0][row] = bv.x; Bs[c4 + 1][row] = bv.y;
            Bs[c4 + 2][row] = bv.z; Bs[c4 + 3][row] = bv.w;
        }
        __syncthreads();

#pragma unroll
        for (int k = 0; k < BK; k++) {
            float4 a0 = *(const float4*)&As[k][ty * 8];
            float4 a1 = *(const float4*)&As[k][ty * 8 + 4];
            float4 b0 = *(const float4*)&Bs[k][tx * 8];
            float4 b1 = *(const float4*)&Bs[k][tx * 8 + 4];
            float ra[8] = {a0.x, a0.y, a0.z, a0.w, a1.x, a1.y, a1.z, a1.w};
            float rb[8] = {b0.x, b0.y, b0.z, b0.w, b1.x, b1.y, b1.z, b1.w};
#pragma unroll
            for (int i = 0; i < 8; i++)
#pragma unroll
                for (int j = 0; j < 8; j++) acc[i][j] += ra[i] * rb[j];
        }
        __syncthreads();
    }

#pragma unroll
    for (int i = 0; i < 8; i++) {
        int r = bm + ty * 8 + i;
        if (r < M) {
#pragma unroll
            for (int j = 0; j < 8; j++) {
                int cidx = bn + tx * 8 + j;
                Cmat[(size_t)r * N + cidx] = acc[i][j] + bias[cidx];
            }
        }
    }
}

// ---------------------------------------------------------------------------
// Fused RMSNorm (over full DIM) + 3D RoPE for q and k. One block per token.
// freqs: [1024][64][2][2] float. pair c: pos = f-idx (c<22), h-idx (c<43), w-idx.
// ---------------------------------------------------------------------------
__global__ void norm_rope_kernel(float* __restrict__ q, float* __restrict__ k,
                                 const float* __restrict__ gq,
                                 const float* __restrict__ gk,
                                 const float* __restrict__ freqs,
                                 const int* __restrict__ grid_sizes) {
    const int l = blockIdx.x;
    const int tid = threadIdx.x;
    __shared__ float red[64];
    __shared__ float s_invq, s_invk;

    float* qr = q + (size_t)l * DIM;
    float* kr = k + (size_t)l * DIM;

    float sq = 0.f, sk = 0.f;
    for (int d = tid; d < DIM; d += blockDim.x) {
        float a = qr[d]; sq += a * a;
        float b = kr[d]; sk += b * b;
    }
#pragma unroll
    for (int o = 16; o; o >>= 1) {
        sq += __shfl_xor_sync(0xffffffffu, sq, o);
        sk += __shfl_xor_sync(0xffffffffu, sk, o);
    }
    int wid = tid >> 5, lid = tid & 31;
    if (lid == 0) { red[wid] = sq; red[32 + wid] = sk; }
    __syncthreads();
    if (tid == 0) {
        float t = 0.f;
        for (int i = 0; i < (int)(blockDim.x >> 5); i++) t += red[i];
        s_invq = rsqrtf(t / DIM + EPS);
    }
    if (tid == 1) {
        float t = 0.f;
        for (int i = 0; i < (int)(blockDim.x >> 5); i++) t += red[32 + i];
        s_invk = rsqrtf(t / DIM + EPS);
    }
    __syncthreads();
    const float invq = s_invq, invk = s_invk;

    const int hh = grid_sizes[1], ww = grid_sizes[2];
    const int hw = hh * ww;
    const int fi = l / hw;
    const int rem = l - fi * hw;
    const int hi = rem / ww;
    const int wi = rem - hi * ww;

    for (int p = tid; p < NH * CPAIR; p += blockDim.x) {
        int c = p & (CPAIR - 1);
        int d0 = (p >> 6) * HD + 2 * c;
        int pos = (c < 22) ? fi : ((c < 43) ? hi : wi);
        const float* R = freqs + ((size_t)pos * CPAIR + c) * 4;
        float r00 = R[0], r01 = R[1], r10 = R[2], r11 = R[3];

        float x0 = qr[d0] * invq * gq[d0];
        float x1 = qr[d0 + 1] * invq * gq[d0 + 1];
        qr[d0]     = r00 * x0 + r01 * x1;
        qr[d0 + 1] = r10 * x0 + r11 * x1;

        x0 = kr[d0] * invk * gk[d0];
        x1 = kr[d0 + 1] * invk * gk[d0 + 1];
        kr[d0]     = r00 * x0 + r01 * x1;
        kr[d0 + 1] = r10 * x0 + r11 * x1;
    }
}

// ---------------------------------------------------------------------------
// Flash attention, fp32. Block = 512 threads (16 warps), 128 queries per block,
// one head per blockIdx.y. K/V streamed in chunks of 32 through smem.
// Each warp owns 8 queries; lane = key within chunk for scores, lane = 4 dims
// for the accumulator.
// ---------------------------------------------------------------------------
#define QT 128
#define KC 32
#define SROW 132   // padded row stride (floats), 528B: 16B aligned + conflict free
#define ATT_SMEM ((QT + 2 * KC) * SROW * 4)

__global__ __launch_bounds__(512, 1)
void attn_kernel(const float* __restrict__ Q, const float* __restrict__ K,
                 const float* __restrict__ V, float* __restrict__ O,
                 const int* __restrict__ seq_lens, int Ltot) {
    extern __shared__ float sm[];
    float* Qs = sm;                       // [QT][SROW]
    float* Ks = Qs + QT * SROW;           // [KC][SROW]
    float* Vs = Ks + KC * SROW;           // [KC][SROW]

    const int head = blockIdx.y;
    const int q0 = blockIdx.x * QT;
    const int tid = threadIdx.x;
    const int wid = tid >> 5;
    const int lane = tid & 31;
    const int seqlen = seq_lens[0];

    // load Q tile (zero-padded beyond Ltot)
    for (int i = tid; i < QT * 32; i += 512) {
        int r = i >> 5, c4 = (i & 31) * 4;
        int gq_ = q0 + r;
        float4 v4 = (gq_ < Ltot)
            ? *(const float4*)&Q[(size_t)gq_ * DIM + head * HD + c4]
            : make_float4(0.f, 0.f, 0.f, 0.f);
        *(float4*)&Qs[r * SROW + c4] = v4;
    }

    float m[8], lsum[8], acc[8][4];
#pragma unroll
    for (int qi = 0; qi < 8; qi++) {
        m[qi] = -1e30f; lsum[qi] = 0.f;
        acc[qi][0] = acc[qi][1] = acc[qi][2] = acc[qi][3] = 0.f;
    }
    const int qbase = wid * 8;

    for (int kc = 0; kc < seqlen; kc += KC) {
        __syncthreads();   // protect Ks/Vs from previous iteration's readers
        for (int i = tid; i < KC * 32; i += 512) {
            int r = i >> 5, c4 = (i & 31) * 4;
            int gk_ = kc + r;
            float4 kv4, vv4;
            if (gk_ < seqlen) {
                kv4 = *(const float4*)&K[(size_t)gk_ * DIM + head * HD + c4];
                vv4 = *(const float4*)&V[(size_t)gk_ * DIM + head * HD + c4];
            } else {
                kv4 = make_float4(0.f, 0.f, 0.f, 0.f);
                vv4 = kv4;
            }
            *(float4*)&Ks[r * SROW + c4] = kv4;
            *(float4*)&Vs[r * SROW + c4] = vv4;
        }
        __syncthreads();

        // scores: lane = key
        float s[8];
#pragma unroll
        for (int qi = 0; qi < 8; qi++) s[qi] = 0.f;
#pragma unroll 8
        for (int dq = 0; dq < 32; dq++) {
            float4 kv = *(const float4*)&Ks[lane * SROW + dq * 4];
#pragma unroll
            for (int qi = 0; qi < 8; qi++) {
                float4 qv = *(const float4*)&Qs[(qbase + qi) * SROW + dq * 4];
                s[qi] += qv.x * kv.x + qv.y * kv.y + qv.z * kv.z + qv.w * kv.w;
            }
        }

        const bool valid = (kc + lane) < seqlen;
        float p[8];
#pragma unroll
        for (int qi = 0; qi < 8; qi++) {
            float sv = valid ? s[qi] * ATT_SCALE : -1e30f;
            float mx = sv;
#pragma unroll
            for (int o = 16; o; o >>= 1)
                mx = fmaxf(mx, __shfl_xor_sync(0xffffffffu, mx, o));
            float newm = fmaxf(m[qi], mx);
            float corr = __expf(m[qi] - newm);
            m[qi] = newm;
            float pv = __expf(sv - newm);
            float ps = pv;
#pragma unroll
            for (int o = 16; o; o >>= 1)
                ps += __shfl_xor_sync(0xffffffffu, ps, o);
            lsum[qi] = lsum[qi] * corr + ps;
            acc[qi][0] *= corr; acc[qi][1] *= corr;
            acc[qi][2] *= corr; acc[qi][3] *= corr;
            p[qi] = pv;
        }

        // accumulate: lane owns dims lane*4 .. lane*4+3
#pragma unroll 4
        for (int kk = 0; kk < KC; kk++) {
            float4 vv = *(const float4*)&Vs[kk * SROW + lane * 4];
#pragma unroll
            for (int qi = 0; qi < 8; qi++) {
                float pv = __shfl_sync(0xffffffffu, p[qi], kk);
                acc[qi][0] += pv * vv.x; acc[qi][1] += pv * vv.y;
                acc[qi][2] += pv * vv.z; acc[qi][3] += pv * vv.w;
            }
        }
    }

#pragma unroll
    for (int qi = 0; qi < 8; qi++) {
        int gq_ = q0 + qbase + qi;
        if (gq_ < Ltot) {
            float inv = (lsum[qi] > 0.f) ? 1.0f / lsum[qi] : 0.f;
            float4 o4 = make_float4(acc[qi][0] * inv, acc[qi][1] * inv,
                                    acc[qi][2] * inv, acc[qi][3] * inv);
            *(float4*)&O[(size_t)gq_ * DIM + head * HD + lane * 4] = o4;
        }
    }
}

// ---------------------------------------------------------------------------
// Inputs (metadata order): 0:x 1:Wq 2:bq 3:Wk 4:bk 5:Wv 6:bv 7:Wo 8:bo
//                          9:gq 10:gk 11:seq_lens 12:grid_sizes 13:freqs
// ---------------------------------------------------------------------------
extern "C" void kernel_launch(void* const* d_in, const int* in_sizes, int n_in,
                              void* d_out, int out_size) {
    const float* x  = (const float*)d_in[0];
    const float* Wq = (const float*)d_in[1];
    const float* bq = (const float*)d_in[2];
    const float* Wk = (const float*)d_in[3];
    const float* bk = (const float*)d_in[4];
    const float* Wv = (const float*)d_in[5];
    const float* bv = (const float*)d_in[6];
    const float* Wo = (const float*)d_in[7];
    const float* bo = (const float*)d_in[8];
    const float* gq = (const float*)d_in[9];
    const float* gk = (const float*)d_in[10];
    const int* seq_lens   = (const int*)d_in[11];
    const int* grid_sizes = (const int*)d_in[12];
    const float* freqs    = (const float*)d_in[13];
    float* out = (float*)d_out;

    const int L = in_sizes[0] / DIM;   // 2400

    float *pq, *pk, *pv, *pa;
    cudaGetSymbolAddress((void**)&pq, g_q);
    cudaGetSymbolAddress((void**)&pk, g_k);
    cudaGetSymbolAddress((void**)&pv, g_v);
    cudaGetSymbolAddress((void**)&pa, g_a);

    dim3 gg(DIM / BN, (L + BM - 1) / BM);
    gemm_bias_kernel<<<gg, 256>>>(x, Wq, bq, pq, L, DIM, DIM);
    gemm_bias_kernel<<<gg, 256>>>(x, Wk, bk, pk, L, DIM, DIM);
    gemm_bias_kernel<<<gg, 256>>>(x, Wv, bv, pv, L, DIM, DIM);

    norm_rope_kernel<<<L, 256>>>(pq, pk, gq, gk, freqs, grid_sizes);

    cudaFuncSetAttribute(attn_kernel,
                         cudaFuncAttributeMaxDynamicSharedMemorySize, ATT_SMEM);
    dim3 ga((L + QT - 1) / QT, NH);
    attn_kernel<<<ga, 512, ATT_SMEM>>>(pq, pk, pv, pa, seq_lens, L);

    gemm_bias_kernel<<<gg, 256>>>(pa, Wo, bo, out, L, DIM, DIM);
}

// round 2
// speedup vs baseline: 1.4985x; 1.4985x over previous
#include <cuda_runtime.h>
#include <math.h>

#define DIM 1536
#define NH 12
#define HD 128
#define CPAIR 64
#define MAXL 2400
#define EPS 1e-6f
#define ATT_SCALE 0.08838834764831843f   // 1/sqrt(128)

// ---------------- scratch (device globals; no allocation allowed) ----------
__device__ float g_q[MAXL * DIM];
__device__ float g_k[MAXL * DIM];
__device__ float g_v[MAXL * DIM];
__device__ float g_a[MAXL * DIM];

// ===========================================================================
// tf32 tensor-core GEMM: C[M,N] = A[M,K] @ B[N,K]^T + bias[N]
// 128x128 tile, BK=32, 256 threads (8 warps), warp tile 64x32 (4x4 m16n8k8).
// cp.async double-buffered smem. Inputs rounded to tf32 with cvt.rna.
// ===========================================================================
#define TBK 32
#define TSTR 36                 // padded smem row stride (floats)
#define TILE_F (128 * TSTR)     // 4608 floats per matrix tile
#define BUF_F (2 * TILE_F)      // A + B per buffer
#define GEMM_SMEM (2 * BUF_F * 4)  // 73728 bytes

__device__ __forceinline__ float to_tf32(float x) {
    float y;
    asm("cvt.rna.tf32.f32 %0, %1;" : "=f"(y) : "f"(x));
    return y;
}

__device__ __forceinline__ unsigned smem_u32(const void* p) {
    unsigned a;
    asm("{.reg .u64 t; cvta.to.shared.u64 t, %1; cvt.u32.u64 %0, t;}"
        : "=r"(a) : "l"(p));
    return a;
}

__device__ __forceinline__ void mma8(float* c, const float* a, const float* b) {
    asm volatile(
        "mma.sync.aligned.m16n8k8.row.col.f32.tf32.tf32.f32 "
        "{%0,%1,%2,%3}, {%4,%5,%6,%7}, {%8,%9}, {%0,%1,%2,%3};\n"
        : "+f"(c[0]), "+f"(c[1]), "+f"(c[2]), "+f"(c[3])
        : "r"(__float_as_uint(a[0])), "r"(__float_as_uint(a[1])),
          "r"(__float_as_uint(a[2])), "r"(__float_as_uint(a[3])),
          "r"(__float_as_uint(b[0])), "r"(__float_as_uint(b[1])));
}

__device__ __forceinline__ void cp_tile(float* sbuf,
                                        const float* __restrict__ A,
                                        const float* __restrict__ B,
                                        int bm, int bn, int M, int K,
                                        int kt, int tid) {
    float* As = sbuf;
    float* Bs = sbuf + TILE_F;
#pragma unroll
    for (int i = 0; i < 4; i++) {
        int slot = tid + i * 256;        // 0..1023 float4 slots per matrix
        int row = slot >> 3;             // 0..127
        int c4 = (slot & 7) * 4;         // 0..28
        int gr = bm + row;
        int grc = (gr < M) ? gr : (M - 1);
        int szA = (gr < M) ? 16 : 0;     // zero-fill out-of-range rows
        const float* gA = A + (size_t)grc * K + kt + c4;
        unsigned sa = smem_u32(&As[row * TSTR + c4]);
        asm volatile("cp.async.cg.shared.global [%0], [%1], 16, %2;\n"
                     :: "r"(sa), "l"(gA), "r"(szA));
        const float* gB = B + (size_t)(bn + row) * K + kt + c4;
        unsigned sb = smem_u32(&Bs[row * TSTR + c4]);
        asm volatile("cp.async.cg.shared.global [%0], [%1], 16;\n"
                     :: "r"(sb), "l"(gB));
    }
    asm volatile("cp.async.commit_group;\n");
}

__device__ __forceinline__ void compute_tile(const float* sbuf,
                                             float acc[4][4][4],
                                             int warp_m, int warp_n,
                                             int gid, int tig) {
    const float* As = sbuf;
    const float* Bs = sbuf + TILE_F;
#pragma unroll
    for (int ka = 0; ka < 4; ka++) {
        int k0 = ka * 8;
        float af[4][4], bf[4][2];
#pragma unroll
        for (int ma = 0; ma < 4; ma++) {
            int r0 = warp_m * 64 + ma * 16 + gid;
            af[ma][0] = to_tf32(As[r0 * TSTR + k0 + tig]);
            af[ma][1] = to_tf32(As[(r0 + 8) * TSTR + k0 + tig]);
            af[ma][2] = to_tf32(As[r0 * TSTR + k0 + tig + 4]);
            af[ma][3] = to_tf32(As[(r0 + 8) * TSTR + k0 + tig + 4]);
        }
#pragma unroll
        for (int na = 0; na < 4; na++) {
            int c0 = warp_n * 32 + na * 8 + gid;
            bf[na][0] = to_tf32(Bs[c0 * TSTR + k0 + tig]);
            bf[na][1] = to_tf32(Bs[c0 * TSTR + k0 + tig + 4]);
        }
#pragma unroll
        for (int ma = 0; ma < 4; ma++)
#pragma unroll
            for (int na = 0; na < 4; na++)
                mma8(acc[ma][na], af[ma], bf[na]);
    }
}

__global__ __launch_bounds__(256, 2)
void gemm_tf32_kernel(const float* __restrict__ A, const float* __restrict__ B,
                      const float* __restrict__ bias, float* __restrict__ C,
                      int M, int N, int K) {
    extern __shared__ float sm[];
    const int tid = threadIdx.x;
    const int lane = tid & 31;
    const int wid = tid >> 5;
    const int gid = lane >> 2, tig = lane & 3;
    const int warp_m = wid >> 2, warp_n = wid & 3;
    const int bm = blockIdx.y * 128, bn = blockIdx.x * 128;

    float acc[4][4][4];
#pragma unroll
    for (int i = 0; i < 4; i++)
#pragma unroll
        for (int j = 0; j < 4; j++)
#pragma unroll
            for (int r = 0; r < 4; r++) acc[i][j][r] = 0.f;

    const int nt = K / TBK;   // 48

    cp_tile(sm, A, B, bm, bn, M, K, 0, tid);

    for (int t = 0; t < nt; t++) {
        if (t + 1 < nt) {
            cp_tile(sm + ((t + 1) & 1) * BUF_F, A, B, bm, bn, M, K,
                    (t + 1) * TBK, tid);
            asm volatile("cp.async.wait_group 1;\n");
        } else {
            asm volatile("cp.async.wait_group 0;\n");
        }
        __syncthreads();
        compute_tile(sm + (t & 1) * BUF_F, acc, warp_m, warp_n, gid, tig);
        __syncthreads();
    }

#pragma unroll
    for (int ma = 0; ma < 4; ma++) {
        int r = bm + warp_m * 64 + ma * 16 + gid;
#pragma unroll
        for (int na = 0; na < 4; na++) {
            int c = bn + warp_n * 32 + na * 8 + tig * 2;
            float2 bb = *(const float2*)&bias[c];
            if (r < M) {
                float2 o = make_float2(acc[ma][na][0] + bb.x,
                                       acc[ma][na][1] + bb.y);
                *(float2*)&C[(size_t)r * N + c] = o;
            }
            if (r + 8 < M) {
                float2 o = make_float2(acc[ma][na][2] + bb.x,
                                       acc[ma][na][3] + bb.y);
                *(float2*)&C[(size_t)(r + 8) * N + c] = o;
            }
        }
    }
}

// ---------------------------------------------------------------------------
// Fused RMSNorm (over full DIM) + 3D RoPE for q and k. One block per token.
// ---------------------------------------------------------------------------
__global__ void norm_rope_kernel(float* __restrict__ q, float* __restrict__ k,
                                 const float* __restrict__ gq,
                                 const float* __restrict__ gk,
                                 const float* __restrict__ freqs,
                                 const int* __restrict__ grid_sizes) {
    const int l = blockIdx.x;
    const int tid = threadIdx.x;
    __shared__ float red[64];
    __shared__ float s_invq, s_invk;

    float* qr = q + (size_t)l * DIM;
    float* kr = k + (size_t)l * DIM;

    float sq = 0.f, sk = 0.f;
    for (int d = tid; d < DIM; d += blockDim.x) {
        float a = qr[d]; sq += a * a;
        float b = kr[d]; sk += b * b;
    }
#pragma unroll
    for (int o = 16; o; o >>= 1) {
        sq += __shfl_xor_sync(0xffffffffu, sq, o);
        sk += __shfl_xor_sync(0xffffffffu, sk, o);
    }
    int wid = tid >> 5, lid = tid & 31;
    if (lid == 0) { red[wid] = sq; red[32 + wid] = sk; }
    __syncthreads();
    if (tid == 0) {
        float t = 0.f;
        for (int i = 0; i < (int)(blockDim.x >> 5); i++) t += red[i];
        s_invq = rsqrtf(t / DIM + EPS);
    }
    if (tid == 1) {
        float t = 0.f;
        for (int i = 0; i < (int)(blockDim.x >> 5); i++) t += red[32 + i];
        s_invk = rsqrtf(t / DIM + EPS);
    }
    __syncthreads();
    const float invq = s_invq, invk = s_invk;

    const int hh = grid_sizes[1], ww = grid_sizes[2];
    const int hw = hh * ww;
    const int fi = l / hw;
    const int rem = l - fi * hw;
    const int hi = rem / ww;
    const int wi = rem - hi * ww;

    for (int p = tid; p < NH * CPAIR; p += blockDim.x) {
        int c = p & (CPAIR - 1);
        int d0 = (p >> 6) * HD + 2 * c;
        int pos = (c < 22) ? fi : ((c < 43) ? hi : wi);
        const float* R = freqs + ((size_t)pos * CPAIR + c) * 4;
        float r00 = R[0], r01 = R[1], r10 = R[2], r11 = R[3];

        float x0 = qr[d0] * invq * gq[d0];
        float x1 = qr[d0 + 1] * invq * gq[d0 + 1];
        qr[d0]     = r00 * x0 + r01 * x1;
        qr[d0 + 1] = r10 * x0 + r11 * x1;

        x0 = kr[d0] * invk * gk[d0];
        x1 = kr[d0 + 1] * invk * gk[d0 + 1];
        kr[d0]     = r00 * x0 + r01 * x1;
        kr[d0 + 1] = r10 * x0 + r11 * x1;
    }
}

// ---------------------------------------------------------------------------
// Flash attention, fp32 (unchanged this round; next target).
// ---------------------------------------------------------------------------
#define QT 128
#define KC 32
#define SROW 132
#define ATT_SMEM ((QT + 2 * KC) * SROW * 4)

__global__ __launch_bounds__(512, 1)
void attn_kernel(const float* __restrict__ Q, const float* __restrict__ K,
                 const float* __restrict__ V, float* __restrict__ O,
                 const int* __restrict__ seq_lens, int Ltot) {
    extern __shared__ float smf[];
    float* Qs = smf;
    float* Ks = Qs + QT * SROW;
    float* Vs = Ks + KC * SROW;

    const int head = blockIdx.y;
    const int q0 = blockIdx.x * QT;
    const int tid = threadIdx.x;
    const int wid = tid >> 5;
    const int lane = tid & 31;
    const int seqlen = seq_lens[0];

    for (int i = tid; i < QT * 32; i += 512) {
        int r = i >> 5, c4 = (i & 31) * 4;
        int gq_ = q0 + r;
        float4 v4 = (gq_ < Ltot)
            ? *(const float4*)&Q[(size_t)gq_ * DIM + head * HD + c4]
            : make_float4(0.f, 0.f, 0.f, 0.f);
        *(float4*)&Qs[r * SROW + c4] = v4;
    }

    float m[8], lsum[8], acc[8][4];
#pragma unroll
    for (int qi = 0; qi < 8; qi++) {
        m[qi] = -1e30f; lsum[qi] = 0.f;
        acc[qi][0] = acc[qi][1] = acc[qi][2] = acc[qi][3] = 0.f;
    }
    const int qbase = wid * 8;

    for (int kc = 0; kc < seqlen; kc += KC) {
        __syncthreads();
        for (int i = tid; i < KC * 32; i += 512) {
            int r = i >> 5, c4 = (i & 31) * 4;
            int gk_ = kc + r;
            float4 kv4, vv4;
            if (gk_ < seqlen) {
                kv4 = *(const float4*)&K[(size_t)gk_ * DIM + head * HD + c4];
                vv4 = *(const float4*)&V[(size_t)gk_ * DIM + head * HD + c4];
            } else {
                kv4 = make_float4(0.f, 0.f, 0.f, 0.f);
                vv4 = kv4;
            }
            *(float4*)&Ks[r * SROW + c4] = kv4;
            *(float4*)&Vs[r * SROW + c4] = vv4;
        }
        __syncthreads();

        float s[8];
#pragma unroll
        for (int qi = 0; qi < 8; qi++) s[qi] = 0.f;
#pragma unroll 8
        for (int dq = 0; dq < 32; dq++) {
            float4 kv = *(const float4*)&Ks[lane * SROW + dq * 4];
#pragma unroll
            for (int qi = 0; qi < 8; qi++) {
                float4 qv = *(const float4*)&Qs[(qbase + qi) * SROW + dq * 4];
                s[qi] += qv.x * kv.x + qv.y * kv.y + qv.z * kv.z + qv.w * kv.w;
            }
        }

        const bool valid = (kc + lane) < seqlen;
        float p[8];
#pragma unroll
        for (int qi = 0; qi < 8; qi++) {
            float sv = valid ? s[qi] * ATT_SCALE : -1e30f;
            float mx = sv;
#pragma unroll
            for (int o = 16; o; o >>= 1)
                mx = fmaxf(mx, __shfl_xor_sync(0xffffffffu, mx, o));
            float newm = fmaxf(m[qi], mx);
            float corr = __expf(m[qi] - newm);
            m[qi] = newm;
            float pv = __expf(sv - newm);
            float ps = pv;
#pragma unroll
            for (int o = 16; o; o >>= 1)
                ps += __shfl_xor_sync(0xffffffffu, ps, o);
            lsum[qi] = lsum[qi] * corr + ps;
            acc[qi][0] *= corr; acc[qi][1] *= corr;
            acc[qi][2] *= corr; acc[qi][3] *= corr;
            p[qi] = pv;
        }

#pragma unroll 4
        for (int kk = 0; kk < KC; kk++) {
            float4 vv = *(const float4*)&Vs[kk * SROW + lane * 4];
#pragma unroll
            for (int qi = 0; qi < 8; qi++) {
                float pv = __shfl_sync(0xffffffffu, p[qi], kk);
                acc[qi][0] += pv * vv.x; acc[qi][1] += pv * vv.y;
                acc[qi][2] += pv * vv.z; acc[qi][3] += pv * vv.w;
            }
        }
    }

#pragma unroll
    for (int qi = 0; qi < 8; qi++) {
        int gq_ = q0 + qbase + qi;
        if (gq_ < Ltot) {
            float inv = (lsum[qi] > 0.f) ? 1.0f / lsum[qi] : 0.f;
            float4 o4 = make_float4(acc[qi][0] * inv, acc[qi][1] * inv,
                                    acc[qi][2] * inv, acc[qi][3] * inv);
            *(float4*)&O[(size_t)gq_ * DIM + head * HD + lane * 4] = o4;
        }
    }
}

// ---------------------------------------------------------------------------
// Inputs: 0:x 1:Wq 2:bq 3:Wk 4:bk 5:Wv 6:bv 7:Wo 8:bo 9:gq 10:gk
//         11:seq_lens 12:grid_sizes 13:freqs
// ---------------------------------------------------------------------------
extern "C" void kernel_launch(void* const* d_in, const int* in_sizes, int n_in,
                              void* d_out, int out_size) {
    const float* x  = (const float*)d_in[0];
    const float* Wq = (const float*)d_in[1];
    const float* bq = (const float*)d_in[2];
    const float* Wk = (const float*)d_in[3];
    const float* bk = (const float*)d_in[4];
    const float* Wv = (const float*)d_in[5];
    const float* bv = (const float*)d_in[6];
    const float* Wo = (const float*)d_in[7];
    const float* bo = (const float*)d_in[8];
    const float* gq = (const float*)d_in[9];
    const float* gk = (const float*)d_in[10];
    const int* seq_lens   = (const int*)d_in[11];
    const int* grid_sizes = (const int*)d_in[12];
    const float* freqs    = (const float*)d_in[13];
    float* out = (float*)d_out;

    const int L = in_sizes[0] / DIM;   // 2400

    float *pq, *pk, *pv, *pa;
    cudaGetSymbolAddress((void**)&pq, g_q);
    cudaGetSymbolAddress((void**)&pk, g_k);
    cudaGetSymbolAddress((void**)&pv, g_v);
    cudaGetSymbolAddress((void**)&pa, g_a);

    cudaFuncSetAttribute(gemm_tf32_kernel,
                         cudaFuncAttributeMaxDynamicSharedMemorySize, GEMM_SMEM);

    dim3 gg(DIM / 128, (L + 127) / 128);
    gemm_tf32_kernel<<<gg, 256, GEMM_SMEM>>>(x, Wq, bq, pq, L, DIM, DIM);
    gemm_tf32_kernel<<<gg, 256, GEMM_SMEM>>>(x, Wk, bk, pk, L, DIM, DIM);
    gemm_tf32_kernel<<<gg, 256, GEMM_SMEM>>>(x, Wv, bv, pv, L, DIM, DIM);

    norm_rope_kernel<<<L, 256>>>(pq, pk, gq, gk, freqs, grid_sizes);

    cudaFuncSetAttribute(attn_kernel,
                         cudaFuncAttributeMaxDynamicSharedMemorySize, ATT_SMEM);
    dim3 ga((L + QT - 1) / QT, NH);
    attn_kernel<<<ga, 512, ATT_SMEM>>>(pq, pk, pv, pa, seq_lens, L);

    gemm_tf32_kernel<<<gg, 256, GEMM_SMEM>>>(pa, Wo, bo, out, L, DIM, DIM);
}

// round 3
// speedup vs baseline: 3.5724x; 2.3840x over previous
#include <cuda_runtime.h>
#include <math.h>

#define DIM 1536
#define NH 12
#define HD 128
#define CPAIR 64
#define MAXL 2400
#define EPS 1e-6f
#define ATT_SCALE 0.08838834764831843f   // 1/sqrt(128)

// ---------------- scratch (device globals; no allocation allowed) ----------
__device__ float g_q[MAXL * DIM];
__device__ float g_k[MAXL * DIM];
__device__ float g_v[MAXL * DIM];
__device__ float g_a[MAXL * DIM];

// ===========================================================================
// common helpers
// ===========================================================================
__device__ __forceinline__ float to_tf32(float x) {
    float y;
    asm("cvt.rna.tf32.f32 %0, %1;" : "=f"(y) : "f"(x));
    return y;
}

__device__ __forceinline__ unsigned smem_u32(const void* p) {
    unsigned a;
    asm("{.reg .u64 t; cvta.to.shared.u64 t, %1; cvt.u32.u64 %0, t;}"
        : "=r"(a) : "l"(p));
    return a;
}

__device__ __forceinline__ void mma8(float* c, const float* a, const float* b) {
    asm volatile(
        "mma.sync.aligned.m16n8k8.row.col.f32.tf32.tf32.f32 "
        "{%0,%1,%2,%3}, {%4,%5,%6,%7}, {%8,%9}, {%0,%1,%2,%3};\n"
        : "+f"(c[0]), "+f"(c[1]), "+f"(c[2]), "+f"(c[3])
        : "r"(__float_as_uint(a[0])), "r"(__float_as_uint(a[1])),
          "r"(__float_as_uint(a[2])), "r"(__float_as_uint(a[3])),
          "r"(__float_as_uint(b[0])), "r"(__float_as_uint(b[1])));
}

__device__ __forceinline__ void mma8b(float* c, const float* a, float b0, float b1) {
    asm volatile(
        "mma.sync.aligned.m16n8k8.row.col.f32.tf32.tf32.f32 "
        "{%0,%1,%2,%3}, {%4,%5,%6,%7}, {%8,%9}, {%0,%1,%2,%3};\n"
        : "+f"(c[0]), "+f"(c[1]), "+f"(c[2]), "+f"(c[3])
        : "r"(__float_as_uint(a[0])), "r"(__float_as_uint(a[1])),
          "r"(__float_as_uint(a[2])), "r"(__float_as_uint(a[3])),
          "r"(__float_as_uint(b0)), "r"(__float_as_uint(b1)));
}

// ===========================================================================
// tf32 tensor-core GEMM: C[M,N] = A[M,K] @ B[N,K]^T + bias[N]   (unchanged)
// ===========================================================================
#define TBK 32
#define TSTR 36
#define TILE_F (128 * TSTR)
#define BUF_F (2 * TILE_F)
#define GEMM_SMEM (2 * BUF_F * 4)

__device__ __forceinline__ void cp_tile(float* sbuf,
                                        const float* __restrict__ A,
                                        const float* __restrict__ B,
                                        int bm, int bn, int M, int K,
                                        int kt, int tid) {
    float* As = sbuf;
    float* Bs = sbuf + TILE_F;
#pragma unroll
    for (int i = 0; i < 4; i++) {
        int slot = tid + i * 256;
        int row = slot >> 3;
        int c4 = (slot & 7) * 4;
        int gr = bm + row;
        int grc = (gr < M) ? gr : (M - 1);
        int szA = (gr < M) ? 16 : 0;
        const float* gA = A + (size_t)grc * K + kt + c4;
        unsigned sa = smem_u32(&As[row * TSTR + c4]);
        asm volatile("cp.async.cg.shared.global [%0], [%1], 16, %2;\n"
                     :: "r"(sa), "l"(gA), "r"(szA));
        const float* gB = B + (size_t)(bn + row) * K + kt + c4;
        unsigned sb = smem_u32(&Bs[row * TSTR + c4]);
        asm volatile("cp.async.cg.shared.global [%0], [%1], 16;\n"
                     :: "r"(sb), "l"(gB));
    }
    asm volatile("cp.async.commit_group;\n");
}

__device__ __forceinline__ void compute_tile(const float* sbuf,
                                             float acc[4][4][4],
                                             int warp_m, int warp_n,
                                             int gid, int tig) {
    const float* As = sbuf;
    const float* Bs = sbuf + TILE_F;
#pragma unroll
    for (int ka = 0; ka < 4; ka++) {
        int k0 = ka * 8;
        float af[4][4], bf[4][2];
#pragma unroll
        for (int ma = 0; ma < 4; ma++) {
            int r0 = warp_m * 64 + ma * 16 + gid;
            af[ma][0] = to_tf32(As[r0 * TSTR + k0 + tig]);
            af[ma][1] = to_tf32(As[(r0 + 8) * TSTR + k0 + tig]);
            af[ma][2] = to_tf32(As[r0 * TSTR + k0 + tig + 4]);
            af[ma][3] = to_tf32(As[(r0 + 8) * TSTR + k0 + tig + 4]);
        }
#pragma unroll
        for (int na = 0; na < 4; na++) {
            int c0 = warp_n * 32 + na * 8 + gid;
            bf[na][0] = to_tf32(Bs[c0 * TSTR + k0 + tig]);
            bf[na][1] = to_tf32(Bs[c0 * TSTR + k0 + tig + 4]);
        }
#pragma unroll
        for (int ma = 0; ma < 4; ma++)
#pragma unroll
            for (int na = 0; na < 4; na++)
                mma8(acc[ma][na], af[ma], bf[na]);
    }
}

__global__ __launch_bounds__(256, 2)
void gemm_tf32_kernel(const float* __restrict__ A, const float* __restrict__ B,
                      const float* __restrict__ bias, float* __restrict__ C,
                      int M, int N, int K) {
    extern __shared__ float sm[];
    const int tid = threadIdx.x;
    const int lane = tid & 31;
    const int wid = tid >> 5;
    const int gid = lane >> 2, tig = lane & 3;
    const int warp_m = wid >> 2, warp_n = wid & 3;
    const int bm = blockIdx.y * 128, bn = blockIdx.x * 128;

    float acc[4][4][4];
#pragma unroll
    for (int i = 0; i < 4; i++)
#pragma unroll
        for (int j = 0; j < 4; j++)
#pragma unroll
            for (int r = 0; r < 4; r++) acc[i][j][r] = 0.f;

    const int nt = K / TBK;

    cp_tile(sm, A, B, bm, bn, M, K, 0, tid);

    for (int t = 0; t < nt; t++) {
        if (t + 1 < nt) {
            cp_tile(sm + ((t + 1) & 1) * BUF_F, A, B, bm, bn, M, K,
                    (t + 1) * TBK, tid);
            asm volatile("cp.async.wait_group 1;\n");
        } else {
            asm volatile("cp.async.wait_group 0;\n");
        }
        __syncthreads();
        compute_tile(sm + (t & 1) * BUF_F, acc, warp_m, warp_n, gid, tig);
        __syncthreads();
    }

#pragma unroll
    for (int ma = 0; ma < 4; ma++) {
        int r = bm + warp_m * 64 + ma * 16 + gid;
#pragma unroll
        for (int na = 0; na < 4; na++) {
            int c = bn + warp_n * 32 + na * 8 + tig * 2;
            float2 bb = *(const float2*)&bias[c];
            if (r < M) {
                float2 o = make_float2(acc[ma][na][0] + bb.x,
                                       acc[ma][na][1] + bb.y);
                *(float2*)&C[(size_t)r * N + c] = o;
            }
            if (r + 8 < M) {
                float2 o = make_float2(acc[ma][na][2] + bb.x,
                                       acc[ma][na][3] + bb.y);
                *(float2*)&C[(size_t)(r + 8) * N + c] = o;
            }
        }
    }
}

// ---------------------------------------------------------------------------
// Fused RMSNorm + 3D RoPE (unchanged)
// ---------------------------------------------------------------------------
__global__ void norm_rope_kernel(float* __restrict__ q, float* __restrict__ k,
                                 const float* __restrict__ gq,
                                 const float* __restrict__ gk,
                                 const float* __restrict__ freqs,
                                 const int* __restrict__ grid_sizes) {
    const int l = blockIdx.x;
    const int tid = threadIdx.x;
    __shared__ float red[64];
    __shared__ float s_invq, s_invk;

    float* qr = q + (size_t)l * DIM;
    float* kr = k + (size_t)l * DIM;

    float sq = 0.f, sk = 0.f;
    for (int d = tid; d < DIM; d += blockDim.x) {
        float a = qr[d]; sq += a * a;
        float b = kr[d]; sk += b * b;
    }
#pragma unroll
    for (int o = 16; o; o >>= 1) {
        sq += __shfl_xor_sync(0xffffffffu, sq, o);
        sk += __shfl_xor_sync(0xffffffffu, sk, o);
    }
    int wid = tid >> 5, lid = tid & 31;
    if (lid == 0) { red[wid] = sq; red[32 + wid] = sk; }
    __syncthreads();
    if (tid == 0) {
        float t = 0.f;
        for (int i = 0; i < (int)(blockDim.x >> 5); i++) t += red[i];
        s_invq = rsqrtf(t / DIM + EPS);
    }
    if (tid == 1) {
        float t = 0.f;
        for (int i = 0; i < (int)(blockDim.x >> 5); i++) t += red[32 + i];
        s_invk = rsqrtf(t / DIM + EPS);
    }
    __syncthreads();
    const float invq = s_invq, invk = s_invk;

    const int hh = grid_sizes[1], ww = grid_sizes[2];
    const int hw = hh * ww;
    const int fi = l / hw;
    const int rem = l - fi * hw;
    const int hi = rem / ww;
    const int wi = rem - hi * ww;

    for (int p = tid; p < NH * CPAIR; p += blockDim.x) {
        int c = p & (CPAIR - 1);
        int d0 = (p >> 6) * HD + 2 * c;
        int pos = (c < 22) ? fi : ((c < 43) ? hi : wi);
        const float* R = freqs + ((size_t)pos * CPAIR + c) * 4;
        float r00 = R[0], r01 = R[1], r10 = R[2], r11 = R[3];

        float x0 = qr[d0] * invq * gq[d0];
        float x1 = qr[d0 + 1] * invq * gq[d0 + 1];
        qr[d0]     = r00 * x0 + r01 * x1;
        qr[d0 + 1] = r10 * x0 + r11 * x1;

        x0 = kr[d0] * invk * gk[d0];
        x1 = kr[d0 + 1] * invk * gk[d0 + 1];
        kr[d0]     = r00 * x0 + r01 * x1;
        kr[d0 + 1] = r10 * x0 + r11 * x1;
    }
}

// ===========================================================================
// tf32 tensor-core flash attention.
// Block: 1 head x 64 queries, 128 threads (4 warps, warp = 16 q-rows).
// K/V chunks of 64 keys. Q frags in registers; K in smem [64][132];
// V transposed in smem [128][68]; P via per-warp smem [64][68].
// ===========================================================================
#define AQT 64
#define AKC 64
#define KSTR 132
#define VSTR 68
#define PSTR 68
#define ASMEM ((AKC * KSTR + HD * VSTR + AQT * PSTR) * 4)   // 86016 B

__global__ __launch_bounds__(128, 2)
void attn_mma_kernel(const float* __restrict__ Q, const float* __restrict__ K,
                     const float* __restrict__ V, float* __restrict__ O,
                     const int* __restrict__ seq_lens, int Ltot) {
    extern __shared__ float sm[];
    float* Ks = sm;                       // [AKC][KSTR]
    float* Vt = Ks + AKC * KSTR;          // [HD][VSTR]   (dim-major, key minor)
    float* Ps = Vt + HD * VSTR;           // [AQT][PSTR]

    const int head = blockIdx.y;
    const int q0 = blockIdx.x * AQT;
    const int tid = threadIdx.x;
    const int w = tid >> 5;
    const int lane = tid & 31;
    const int gid = lane >> 2, tig = lane & 3;
    const int seqlen = seq_lens[0];

    // ---- Q fragments (registers, tf32-rounded once) ----
    const int r0 = q0 + w * 16 + gid;
    const int r1 = r0 + 8;
    const float* q0p = Q + (size_t)((r0 < Ltot) ? r0 : (Ltot - 1)) * DIM + head * HD;
    const float* q1p = Q + (size_t)((r1 < Ltot) ? r1 : (Ltot - 1)) * DIM + head * HD;
    float qa[16][4];
#pragma unroll
    for (int c = 0; c < 16; c++) {
        qa[c][0] = to_tf32(q0p[c * 8 + tig]);
        qa[c][1] = to_tf32(q1p[c * 8 + tig]);
        qa[c][2] = to_tf32(q0p[c * 8 + tig + 4]);
        qa[c][3] = to_tf32(q1p[c * 8 + tig + 4]);
    }

    float oacc[16][4];
#pragma unroll
    for (int i = 0; i < 16; i++)
#pragma unroll
        for (int j = 0; j < 4; j++) oacc[i][j] = 0.f;
    float m0 = -1e30f, m1 = -1e30f, l0 = 0.f, l1 = 0.f;

    const int nchunk = (seqlen + AKC - 1) / AKC;
    for (int ch = 0; ch < nchunk; ch++) {
        const int kc = ch * AKC;
        __syncthreads();   // protect Ks/Vt from previous iteration's readers

        // ---- load K chunk: [64 keys][128 dims], tf32-rounded ----
#pragma unroll
        for (int it = 0; it < 16; it++) {
            int s = tid + it * 128;
            int key = s >> 5, c4 = (s & 31) * 4;
            int gk = kc + key;
            float4 kv = (gk < seqlen)
                ? *(const float4*)&K[(size_t)gk * DIM + head * HD + c4]
                : make_float4(0.f, 0.f, 0.f, 0.f);
            float* d = &Ks[key * KSTR + c4];
            d[0] = to_tf32(kv.x); d[1] = to_tf32(kv.y);
            d[2] = to_tf32(kv.z); d[3] = to_tf32(kv.w);
        }
        // ---- load V chunk transposed: Vt[dim][key] ----
#pragma unroll
        for (int it = 0; it < 8; it++) {
            int s = tid + it * 128;
            int key = s & 63, g2 = s >> 6;   // g2: 0..15, 8 dims each
            int gk = kc + key;
            float4 v0, v1;
            if (gk < seqlen) {
                const float* vp = &V[(size_t)gk * DIM + head * HD + g2 * 8];
                v0 = *(const float4*)vp;
                v1 = *(const float4*)(vp + 4);
            } else {
                v0 = make_float4(0.f, 0.f, 0.f, 0.f); v1 = v0;
            }
            int db = g2 * 8;
            Vt[(db + 0) * VSTR + key] = to_tf32(v0.x);
            Vt[(db + 1) * VSTR + key] = to_tf32(v0.y);
            Vt[(db + 2) * VSTR + key] = to_tf32(v0.z);
            Vt[(db + 3) * VSTR + key] = to_tf32(v0.w);
            Vt[(db + 4) * VSTR + key] = to_tf32(v1.x);
            Vt[(db + 5) * VSTR + key] = to_tf32(v1.y);
            Vt[(db + 6) * VSTR + key] = to_tf32(v1.z);
            Vt[(db + 7) * VSTR + key] = to_tf32(v1.w);
        }
        __syncthreads();

        // ---- S = Q @ K^T : [16 rows][64 keys] per warp ----
        float sacc[8][4];
#pragma unroll
        for (int na = 0; na < 8; na++)
#pragma unroll
            for (int j = 0; j < 4; j++) sacc[na][j] = 0.f;
#pragma unroll
        for (int kk = 0; kk < 16; kk++) {
#pragma unroll
            for (int na = 0; na < 8; na++) {
                const float* kb = &Ks[(na * 8 + gid) * KSTR + kk * 8 + tig];
                mma8b(sacc[na], qa[kk], kb[0], kb[4]);
            }
        }

        // ---- online softmax on fragments ----
        float mx0 = -1e30f, mx1 = -1e30f;
#pragma unroll
        for (int na = 0; na < 8; na++) {
            int col = kc + na * 8 + 2 * tig;
            bool ok0 = col < seqlen, ok1 = (col + 1) < seqlen;
            sacc[na][0] = ok0 ? sacc[na][0] * ATT_SCALE : -1e30f;
            sacc[na][1] = ok1 ? sacc[na][1] * ATT_SCALE : -1e30f;
            sacc[na][2] = ok0 ? sacc[na][2] * ATT_SCALE : -1e30f;
            sacc[na][3] = ok1 ? sacc[na][3] * ATT_SCALE : -1e30f;
            mx0 = fmaxf(mx0, fmaxf(sacc[na][0], sacc[na][1]));
            mx1 = fmaxf(mx1, fmaxf(sacc[na][2], sacc[na][3]));
        }
#pragma unroll
        for (int o = 1; o <= 2; o <<= 1) {
            mx0 = fmaxf(mx0, __shfl_xor_sync(0xffffffffu, mx0, o));
            mx1 = fmaxf(mx1, __shfl_xor_sync(0xffffffffu, mx1, o));
        }
        float nm0 = fmaxf(m0, mx0), nm1 = fmaxf(m1, mx1);
        float c0 = __expf(m0 - nm0), c1 = __expf(m1 - nm1);
        m0 = nm0; m1 = nm1;

        float ps0 = 0.f, ps1 = 0.f;
        const int prow = w * 16 + gid;
#pragma unroll
        for (int na = 0; na < 8; na++) {
            float p0 = __expf(sacc[na][0] - m0);
            float p1 = __expf(sacc[na][1] - m0);
            float p2 = __expf(sacc[na][2] - m1);
            float p3 = __expf(sacc[na][3] - m1);
            ps0 += p0 + p1; ps1 += p2 + p3;
            float2 w0 = make_float2(to_tf32(p0), to_tf32(p1));
            float2 w1 = make_float2(to_tf32(p2), to_tf32(p3));
            *(float2*)&Ps[prow * PSTR + na * 8 + 2 * tig] = w0;
            *(float2*)&Ps[(prow + 8) * PSTR + na * 8 + 2 * tig] = w1;
        }
#pragma unroll
        for (int o = 1; o <= 2; o <<= 1) {
            ps0 += __shfl_xor_sync(0xffffffffu, ps0, o);
            ps1 += __shfl_xor_sync(0xffffffffu, ps1, o);
        }
        l0 = l0 * c0 + ps0;
        l1 = l1 * c1 + ps1;
#pragma unroll
        for (int na = 0; na < 16; na++) {
            oacc[na][0] *= c0; oacc[na][1] *= c0;
            oacc[na][2] *= c1; oacc[na][3] *= c1;
        }
        __syncwarp();

        // ---- O += P @ V ----
#pragma unroll
        for (int kk = 0; kk < 8; kk++) {
            float pa[4];
            pa[0] = Ps[prow * PSTR + kk * 8 + tig];
            pa[1] = Ps[(prow + 8) * PSTR + kk * 8 + tig];
            pa[2] = Ps[prow * PSTR + kk * 8 + tig + 4];
            pa[3] = Ps[(prow + 8) * PSTR + kk * 8 + tig + 4];
#pragma unroll
            for (int na = 0; na < 16; na++) {
                const float* vb = &Vt[(na * 8 + gid) * VSTR + kk * 8 + tig];
                mma8b(oacc[na], pa, vb[0], vb[4]);
            }
        }
        __syncwarp();
    }

    // ---- epilogue ----
    float inv0 = (l0 > 0.f) ? 1.0f / l0 : 0.f;
    float inv1 = (l1 > 0.f) ? 1.0f / l1 : 0.f;
#pragma unroll
    for (int na = 0; na < 16; na++) {
        int c = head * HD + na * 8 + 2 * tig;
        if (r0 < Ltot) {
            float2 o = make_float2(oacc[na][0] * inv0, oacc[na][1] * inv0);
            *(float2*)&O[(size_t)r0 * DIM + c] = o;
        }
        if (r1 < Ltot) {
            float2 o = make_float2(oacc[na][2] * inv1, oacc[na][3] * inv1);
            *(float2*)&O[(size_t)r1 * DIM + c] = o;
        }
    }
}

// ---------------------------------------------------------------------------
// Inputs: 0:x 1:Wq 2:bq 3:Wk 4:bk 5:Wv 6:bv 7:Wo 8:bo 9:gq 10:gk
//         11:seq_lens 12:grid_sizes 13:freqs
// ---------------------------------------------------------------------------
extern "C" void kernel_launch(void* const* d_in, const int* in_sizes, int n_in,
                              void* d_out, int out_size) {
    const float* x  = (const float*)d_in[0];
    const float* Wq = (const float*)d_in[1];
    const float* bq = (const float*)d_in[2];
    const float* Wk = (const float*)d_in[3];
    const float* bk = (const float*)d_in[4];
    const float* Wv = (const float*)d_in[5];
    const float* bv = (const float*)d_in[6];
    const float* Wo = (const float*)d_in[7];
    const float* bo = (const float*)d_in[8];
    const float* gq = (const float*)d_in[9];
    const float* gk = (const float*)d_in[10];
    const int* seq_lens   = (const int*)d_in[11];
    const int* grid_sizes = (const int*)d_in[12];
    const float* freqs    = (const float*)d_in[13];
    float* out = (float*)d_out;

    const int L = in_sizes[0] / DIM;   // 2400

    float *pq, *pk, *pv, *pa;
    cudaGetSymbolAddress((void**)&pq, g_q);
    cudaGetSymbolAddress((void**)&pk, g_k);
    cudaGetSymbolAddress((void**)&pv, g_v);
    cudaGetSymbolAddress((void**)&pa, g_a);

    cudaFuncSetAttribute(gemm_tf32_kernel,
                         cudaFuncAttributeMaxDynamicSharedMemorySize, GEMM_SMEM);
    cudaFuncSetAttribute(attn_mma_kernel,
                         cudaFuncAttributeMaxDynamicSharedMemorySize, ASMEM);

    dim3 gg(DIM / 128, (L + 127) / 128);
    gemm_tf32_kernel<<<gg, 256, GEMM_SMEM>>>(x, Wq, bq, pq, L, DIM, DIM);
    gemm_tf32_kernel<<<gg, 256, GEMM_SMEM>>>(x, Wk, bk, pk, L, DIM, DIM);
    gemm_tf32_kernel<<<gg, 256, GEMM_SMEM>>>(x, Wv, bv, pv, L, DIM, DIM);

    norm_rope_kernel<<<L, 256>>>(pq, pk, gq, gk, freqs, grid_sizes);

    dim3 ga((L + AQT - 1) / AQT, NH);
    attn_mma_kernel<<<ga, 128, ASMEM>>>(pq, pk, pv, pa, seq_lens, L);

    gemm_tf32_kernel<<<gg, 256, GEMM_SMEM>>>(pa, Wo, bo, out, L, DIM, DIM);
}

// round 4
// speedup vs baseline: 3.9293x; 1.0999x over previous
#include <cuda_runtime.h>
#include <math.h>

#define DIM 1536
#define NH 12
#define HD 128
#define CPAIR 64
#define MAXL 2400
#define EPS 1e-6f
#define ATT_SCALE 0.08838834764831843f   // 1/sqrt(128)

// ---------------- scratch (device globals; no allocation allowed) ----------
__device__ float g_q[MAXL * DIM];
__device__ float g_k[MAXL * DIM];
__device__ float g_v[MAXL * DIM];
__device__ float g_a[MAXL * DIM];
__device__ float g_xr[MAXL * DIM];          // tf32-rounded x
__device__ float g_wr[4 * DIM * DIM];       // tf32-rounded Wq,Wk,Wv,Wo

// ===========================================================================
// common helpers
// ===========================================================================
__device__ __forceinline__ float to_tf32(float x) {
    float y;
    asm("cvt.rna.tf32.f32 %0, %1;" : "=f"(y) : "f"(x));
    return y;
}

__device__ __forceinline__ unsigned smem_u32(const void* p) {
    unsigned a;
    asm("{.reg .u64 t; cvta.to.shared.u64 t, %1; cvt.u32.u64 %0, t;}"
        : "=r"(a) : "l"(p));
    return a;
}

__device__ __forceinline__ void mma8(float* c, const float* a, const float* b) {
    asm volatile(
        "mma.sync.aligned.m16n8k8.row.col.f32.tf32.tf32.f32 "
        "{%0,%1,%2,%3}, {%4,%5,%6,%7}, {%8,%9}, {%0,%1,%2,%3};\n"
        : "+f"(c[0]), "+f"(c[1]), "+f"(c[2]), "+f"(c[3])
        : "r"(__float_as_uint(a[0])), "r"(__float_as_uint(a[1])),
          "r"(__float_as_uint(a[2])), "r"(__float_as_uint(a[3])),
          "r"(__float_as_uint(b[0])), "r"(__float_as_uint(b[1])));
}

__device__ __forceinline__ void mma8b(float* c, const float* a, float b0, float b1) {
    asm volatile(
        "mma.sync.aligned.m16n8k8.row.col.f32.tf32.tf32.f32 "
        "{%0,%1,%2,%3}, {%4,%5,%6,%7}, {%8,%9}, {%0,%1,%2,%3};\n"
        : "+f"(c[0]), "+f"(c[1]), "+f"(c[2]), "+f"(c[3])
        : "r"(__float_as_uint(a[0])), "r"(__float_as_uint(a[1])),
          "r"(__float_as_uint(a[2])), "r"(__float_as_uint(a[3])),
          "r"(__float_as_uint(b0)), "r"(__float_as_uint(b1)));
}

// ===========================================================================
// tf32 pre-rounding pass (hoists cvt out of all GEMM inner loops)
// ===========================================================================
__global__ void round_tf32_kernel(const float* __restrict__ in,
                                  float* __restrict__ out, int n4) {
    int i = blockIdx.x * blockDim.x + threadIdx.x;
    if (i < n4) {
        float4 v = ((const float4*)in)[i];
        v.x = to_tf32(v.x); v.y = to_tf32(v.y);
        v.z = to_tf32(v.z); v.w = to_tf32(v.w);
        ((float4*)out)[i] = v;
    }
}

// ===========================================================================
// tf32 tensor-core GEMM core: C[M,N] = A[M,K] @ B[N,K]^T + bias[N]
// Inputs MUST already be tf32-rounded. 128x128 tile, BK=32, 256 threads.
// ===========================================================================
#define TBK 32
#define TSTR 36
#define TILE_F (128 * TSTR)
#define BUF_F (2 * TILE_F)
#define GEMM_SMEM (2 * BUF_F * 4)

__device__ __forceinline__ void cp_tile(float* sbuf,
                                        const float* __restrict__ A,
                                        const float* __restrict__ B,
                                        int bm, int bn, int M, int K,
                                        int kt, int tid) {
    float* As = sbuf;
    float* Bs = sbuf + TILE_F;
#pragma unroll
    for (int i = 0; i < 4; i++) {
        int slot = tid + i * 256;
        int row = slot >> 3;
        int c4 = (slot & 7) * 4;
        int gr = bm + row;
        int grc = (gr < M) ? gr : (M - 1);
        int szA = (gr < M) ? 16 : 0;
        const float* gA = A + (size_t)grc * K + kt + c4;
        unsigned sa = smem_u32(&As[row * TSTR + c4]);
        asm volatile("cp.async.cg.shared.global [%0], [%1], 16, %2;\n"
                     :: "r"(sa), "l"(gA), "r"(szA));
        const float* gB = B + (size_t)(bn + row) * K + kt + c4;
        unsigned sb = smem_u32(&Bs[row * TSTR + c4]);
        asm volatile("cp.async.cg.shared.global [%0], [%1], 16;\n"
                     :: "r"(sb), "l"(gB));
    }
    asm volatile("cp.async.commit_group;\n");
}

__device__ __forceinline__ void compute_tile(const float* sbuf,
                                             float acc[4][4][4],
                                             int warp_m, int warp_n,
                                             int gid, int tig) {
    const float* As = sbuf;
    const float* Bs = sbuf + TILE_F;
#pragma unroll
    for (int ka = 0; ka < 4; ka++) {
        int k0 = ka * 8;
        float af[4][4], bf[4][2];
#pragma unroll
        for (int ma = 0; ma < 4; ma++) {
            int r0 = warp_m * 64 + ma * 16 + gid;
            af[ma][0] = As[r0 * TSTR + k0 + tig];
            af[ma][1] = As[(r0 + 8) * TSTR + k0 + tig];
            af[ma][2] = As[r0 * TSTR + k0 + tig + 4];
            af[ma][3] = As[(r0 + 8) * TSTR + k0 + tig + 4];
        }
#pragma unroll
        for (int na = 0; na < 4; na++) {
            int c0 = warp_n * 32 + na * 8 + gid;
            bf[na][0] = Bs[c0 * TSTR + k0 + tig];
            bf[na][1] = Bs[c0 * TSTR + k0 + tig + 4];
        }
#pragma unroll
        for (int ma = 0; ma < 4; ma++)
#pragma unroll
            for (int na = 0; na < 4; na++)
                mma8(acc[ma][na], af[ma], bf[na]);
    }
}

__device__ __forceinline__ void gemm_body(const float* __restrict__ A,
                                          const float* __restrict__ B,
                                          const float* __restrict__ bias,
                                          float* __restrict__ C,
                                          int M, int N, int K,
                                          bool roundOut, float* sm) {
    const int tid = threadIdx.x;
    const int lane = tid & 31;
    const int wid = tid >> 5;
    const int gid = lane >> 2, tig = lane & 3;
    const int warp_m = wid >> 2, warp_n = wid & 3;
    const int bm = blockIdx.y * 128, bn = blockIdx.x * 128;

    float acc[4][4][4];
#pragma unroll
    for (int i = 0; i < 4; i++)
#pragma unroll
        for (int j = 0; j < 4; j++)
#pragma unroll
            for (int r = 0; r < 4; r++) acc[i][j][r] = 0.f;

    const int nt = K / TBK;

    cp_tile(sm, A, B, bm, bn, M, K, 0, tid);

    for (int t = 0; t < nt; t++) {
        if (t + 1 < nt) {
            cp_tile(sm + ((t + 1) & 1) * BUF_F, A, B, bm, bn, M, K,
                    (t + 1) * TBK, tid);
            asm volatile("cp.async.wait_group 1;\n");
        } else {
            asm volatile("cp.async.wait_group 0;\n");
        }
        __syncthreads();
        compute_tile(sm + (t & 1) * BUF_F, acc, warp_m, warp_n, gid, tig);
        __syncthreads();
    }

#pragma unroll
    for (int ma = 0; ma < 4; ma++) {
        int r = bm + warp_m * 64 + ma * 16 + gid;
#pragma unroll
        for (int na = 0; na < 4; na++) {
            int c = bn + warp_n * 32 + na * 8 + tig * 2;
            float2 bb = *(const float2*)&bias[c];
            float2 o0 = make_float2(acc[ma][na][0] + bb.x, acc[ma][na][1] + bb.y);
            float2 o1 = make_float2(acc[ma][na][2] + bb.x, acc[ma][na][3] + bb.y);
            if (roundOut) {
                o0.x = to_tf32(o0.x); o0.y = to_tf32(o0.y);
                o1.x = to_tf32(o1.x); o1.y = to_tf32(o1.y);
            }
            if (r < M)     *(float2*)&C[(size_t)r * N + c] = o0;
            if (r + 8 < M) *(float2*)&C[(size_t)(r + 8) * N + c] = o1;
        }
    }
}

// Fused QKV: blockIdx.z selects weight slab / bias / destination. Rounds output.
__global__ __launch_bounds__(256, 2)
void gemm_qkv_kernel(const float* __restrict__ A, const float* __restrict__ W,
                     const float* __restrict__ bq, const float* __restrict__ bk,
                     const float* __restrict__ bv,
                     float* __restrict__ Cq, float* __restrict__ Ck,
                     float* __restrict__ Cv, int M) {
    extern __shared__ float sm[];
    const int z = blockIdx.z;
    const float* B = W + (size_t)z * DIM * DIM;
    const float* bias = (z == 0) ? bq : (z == 1) ? bk : bv;
    float* C = (z == 0) ? Cq : (z == 1) ? Ck : Cv;
    gemm_body(A, B, bias, C, M, DIM, DIM, true, sm);
}

// Single GEMM (output projection), no output rounding.
__global__ __launch_bounds__(256, 2)
void gemm_tf32_kernel(const float* __restrict__ A, const float* __restrict__ B,
                      const float* __restrict__ bias, float* __restrict__ C,
                      int M, int N, int K) {
    extern __shared__ float sm[];
    gemm_body(A, B, bias, C, M, N, K, false, sm);
}

// ---------------------------------------------------------------------------
// Fused RMSNorm + 3D RoPE; emits tf32-rounded q/k.
// ---------------------------------------------------------------------------
__global__ void norm_rope_kernel(float* __restrict__ q, float* __restrict__ k,
                                 const float* __restrict__ gq,
                                 const float* __restrict__ gk,
                                 const float* __restrict__ freqs,
                                 const int* __restrict__ grid_sizes) {
    const int l = blockIdx.x;
    const int tid = threadIdx.x;
    __shared__ float red[64];
    __shared__ float s_invq, s_invk;

    float* qr = q + (size_t)l * DIM;
    float* kr = k + (size_t)l * DIM;

    float sq = 0.f, sk = 0.f;
    for (int d = tid; d < DIM; d += blockDim.x) {
        float a = qr[d]; sq += a * a;
        float b = kr[d]; sk += b * b;
    }
#pragma unroll
    for (int o = 16; o; o >>= 1) {
        sq += __shfl_xor_sync(0xffffffffu, sq, o);
        sk += __shfl_xor_sync(0xffffffffu, sk, o);
    }
    int wid = tid >> 5, lid = tid & 31;
    if (lid == 0) { red[wid] = sq; red[32 + wid] = sk; }
    __syncthreads();
    if (tid == 0) {
        float t = 0.f;
        for (int i = 0; i < (int)(blockDim.x >> 5); i++) t += red[i];
        s_invq = rsqrtf(t / DIM + EPS);
    }
    if (tid == 1) {
        float t = 0.f;
        for (int i = 0; i < (int)(blockDim.x >> 5); i++) t += red[32 + i];
        s_invk = rsqrtf(t / DIM + EPS);
    }
    __syncthreads();
    const float invq = s_invq, invk = s_invk;

    const int hh = grid_sizes[1], ww = grid_sizes[2];
    const int hw = hh * ww;
    const int fi = l / hw;
    const int rem = l - fi * hw;
    const int hi = rem / ww;
    const int wi = rem - hi * ww;

    for (int p = tid; p < NH * CPAIR; p += blockDim.x) {
        int c = p & (CPAIR - 1);
        int d0 = (p >> 6) * HD + 2 * c;
        int pos = (c < 22) ? fi : ((c < 43) ? hi : wi);
        const float* R = freqs + ((size_t)pos * CPAIR + c) * 4;
        float r00 = R[0], r01 = R[1], r10 = R[2], r11 = R[3];

        float x0 = qr[d0] * invq * gq[d0];
        float x1 = qr[d0 + 1] * invq * gq[d0 + 1];
        qr[d0]     = to_tf32(r00 * x0 + r01 * x1);
        qr[d0 + 1] = to_tf32(r10 * x0 + r11 * x1);

        x0 = kr[d0] * invk * gk[d0];
        x1 = kr[d0 + 1] * invk * gk[d0 + 1];
        kr[d0]     = to_tf32(r00 * x0 + r01 * x1);
        kr[d0 + 1] = to_tf32(r10 * x0 + r11 * x1);
    }
}

// ===========================================================================
// tf32 tensor-core flash attention (inputs pre-rounded; output rounded).
// ===========================================================================
#define AQT 64
#define AKC 64
#define KSTR 132
#define VSTR 68
#define PSTR 68
#define ASMEM ((AKC * KSTR + HD * VSTR + AQT * PSTR) * 4)   // 86016 B

__global__ __launch_bounds__(128, 2)
void attn_mma_kernel(const float* __restrict__ Q, const float* __restrict__ K,
                     const float* __restrict__ V, float* __restrict__ O,
                     const int* __restrict__ seq_lens, int Ltot) {
    extern __shared__ float sm[];
    float* Ks = sm;                       // [AKC][KSTR]
    float* Vt = Ks + AKC * KSTR;          // [HD][VSTR]
    float* Ps = Vt + HD * VSTR;           // [AQT][PSTR]

    const int head = blockIdx.y;
    const int q0 = blockIdx.x * AQT;
    const int tid = threadIdx.x;
    const int w = tid >> 5;
    const int lane = tid & 31;
    const int gid = lane >> 2, tig = lane & 3;
    const int seqlen = seq_lens[0];

    const int r0 = q0 + w * 16 + gid;
    const int r1 = r0 + 8;
    const float* q0p = Q + (size_t)((r0 < Ltot) ? r0 : (Ltot - 1)) * DIM + head * HD;
    const float* q1p = Q + (size_t)((r1 < Ltot) ? r1 : (Ltot - 1)) * DIM + head * HD;
    float qa[16][4];
#pragma unroll
    for (int c = 0; c < 16; c++) {
        qa[c][0] = q0p[c * 8 + tig];
        qa[c][1] = q1p[c * 8 + tig];
        qa[c][2] = q0p[c * 8 + tig + 4];
        qa[c][3] = q1p[c * 8 + tig + 4];
    }

    float oacc[16][4];
#pragma unroll
    for (int i = 0; i < 16; i++)
#pragma unroll
        for (int j = 0; j < 4; j++) oacc[i][j] = 0.f;
    float m0 = -1e30f, m1 = -1e30f, l0 = 0.f, l1 = 0.f;

    const int nchunk = (seqlen + AKC - 1) / AKC;
    for (int ch = 0; ch < nchunk; ch++) {
        const int kc = ch * AKC;
        __syncthreads();

        // K chunk (pre-rounded)
#pragma unroll
        for (int it = 0; it < 16; it++) {
            int s = tid + it * 128;
            int key = s >> 5, c4 = (s & 31) * 4;
            int gk = kc + key;
            float4 kv = (gk < seqlen)
                ? *(const float4*)&K[(size_t)gk * DIM + head * HD + c4]
                : make_float4(0.f, 0.f, 0.f, 0.f);
            *(float4*)&Ks[key * KSTR + c4] = kv;
        }
        // V chunk transposed (pre-rounded)
#pragma unroll
        for (int it = 0; it < 8; it++) {
            int s = tid + it * 128;
            int key = s & 63, g2 = s >> 6;
            int gk = kc + key;
            float4 v0, v1;
            if (gk < seqlen) {
                const float* vp = &V[(size_t)gk * DIM + head * HD + g2 * 8];
                v0 = *(const float4*)vp;
                v1 = *(const float4*)(vp + 4);
            } else {
                v0 = make_float4(0.f, 0.f, 0.f, 0.f); v1 = v0;
            }
            int db = g2 * 8;
            Vt[(db + 0) * VSTR + key] = v0.x;
            Vt[(db + 1) * VSTR + key] = v0.y;
            Vt[(db + 2) * VSTR + key] = v0.z;
            Vt[(db + 3) * VSTR + key] = v0.w;
            Vt[(db + 4) * VSTR + key] = v1.x;
            Vt[(db + 5) * VSTR + key] = v1.y;
            Vt[(db + 6) * VSTR + key] = v1.z;
            Vt[(db + 7) * VSTR + key] = v1.w;
        }
        __syncthreads();

        // S = Q @ K^T
        float sacc[8][4];
#pragma unroll
        for (int na = 0; na < 8; na++)
#pragma unroll
            for (int j = 0; j < 4; j++) sacc[na][j] = 0.f;
#pragma unroll
        for (int kk = 0; kk < 16; kk++) {
#pragma unroll
            for (int na = 0; na < 8; na++) {
                const float* kb = &Ks[(na * 8 + gid) * KSTR + kk * 8 + tig];
                mma8b(sacc[na], qa[kk], kb[0], kb[4]);
            }
        }

        // online softmax
        float mx0 = -1e30f, mx1 = -1e30f;
#pragma unroll
        for (int na = 0; na < 8; na++) {
            int col = kc + na * 8 + 2 * tig;
            bool ok0 = col < seqlen, ok1 = (col + 1) < seqlen;
            sacc[na][0] = ok0 ? sacc[na][0] * ATT_SCALE : -1e30f;
            sacc[na][1] = ok1 ? sacc[na][1] * ATT_SCALE : -1e30f;
            sacc[na][2] = ok0 ? sacc[na][2] * ATT_SCALE : -1e30f;
            sacc[na][3] = ok1 ? sacc[na][3] * ATT_SCALE : -1e30f;
            mx0 = fmaxf(mx0, fmaxf(sacc[na][0], sacc[na][1]));
            mx1 = fmaxf(mx1, fmaxf(sacc[na][2], sacc[na][3]));
        }
#pragma unroll
        for (int o = 1; o <= 2; o <<= 1) {
            mx0 = fmaxf(mx0, __shfl_xor_sync(0xffffffffu, mx0, o));
            mx1 = fmaxf(mx1, __shfl_xor_sync(0xffffffffu, mx1, o));
        }
        float nm0 = fmaxf(m0, mx0), nm1 = fmaxf(m1, mx1);
        float c0 = __expf(m0 - nm0), c1 = __expf(m1 - nm1);
        m0 = nm0; m1 = nm1;

        float ps0 = 0.f, ps1 = 0.f;
        const int prow = w * 16 + gid;
#pragma unroll
        for (int na = 0; na < 8; na++) {
            float p0 = __expf(sacc[na][0] - m0);
            float p1 = __expf(sacc[na][1] - m0);
            float p2 = __expf(sacc[na][2] - m1);
            float p3 = __expf(sacc[na][3] - m1);
            ps0 += p0 + p1; ps1 += p2 + p3;
            float2 w0 = make_float2(to_tf32(p0), to_tf32(p1));
            float2 w1 = make_float2(to_tf32(p2), to_tf32(p3));
            *(float2*)&Ps[prow * PSTR + na * 8 + 2 * tig] = w0;
            *(float2*)&Ps[(prow + 8) * PSTR + na * 8 + 2 * tig] = w1;
        }
#pragma unroll
        for (int o = 1; o <= 2; o <<= 1) {
            ps0 += __shfl_xor_sync(0xffffffffu, ps0, o);
            ps1 += __shfl_xor_sync(0xffffffffu, ps1, o);
        }
        l0 = l0 * c0 + ps0;
        l1 = l1 * c1 + ps1;
#pragma unroll
        for (int na = 0; na < 16; na++) {
            oacc[na][0] *= c0; oacc[na][1] *= c0;
            oacc[na][2] *= c1; oacc[na][3] *= c1;
        }
        __syncwarp();

        // O += P @ V
#pragma unroll
        for (int kk = 0; kk < 8; kk++) {
            float pa[4];
            pa[0] = Ps[prow * PSTR + kk * 8 + tig];
            pa[1] = Ps[(prow + 8) * PSTR + kk * 8 + tig];
            pa[2] = Ps[prow * PSTR + kk * 8 + tig + 4];
            pa[3] = Ps[(prow + 8) * PSTR + kk * 8 + tig + 4];
#pragma unroll
            for (int na = 0; na < 16; na++) {
                const float* vb = &Vt[(na * 8 + gid) * VSTR + kk * 8 + tig];
                mma8b(oacc[na], pa, vb[0], vb[4]);
            }
        }
        __syncwarp();
    }

    // epilogue: tf32-rounded (consumed by tf32 GEMM)
    float inv0 = (l0 > 0.f) ? 1.0f / l0 : 0.f;
    float inv1 = (l1 > 0.f) ? 1.0f / l1 : 0.f;
#pragma unroll
    for (int na = 0; na < 16; na++) {
        int c = head * HD + na * 8 + 2 * tig;
        if (r0 < Ltot) {
            float2 o = make_float2(to_tf32(oacc[na][0] * inv0),
                                   to_tf32(oacc[na][1] * inv0));
            *(float2*)&O[(size_t)r0 * DIM + c] = o;
        }
        if (r1 < Ltot) {
            float2 o = make_float2(to_tf32(oacc[na][2] * inv1),
                                   to_tf32(oacc[na][3] * inv1));
            *(float2*)&O[(size_t)r1 * DIM + c] = o;
        }
    }
}

// ---------------------------------------------------------------------------
// Inputs: 0:x 1:Wq 2:bq 3:Wk 4:bk 5:Wv 6:bv 7:Wo 8:bo 9:gq 10:gk
//         11:seq_lens 12:grid_sizes 13:freqs
// ---------------------------------------------------------------------------
extern "C" void kernel_launch(void* const* d_in, const int* in_sizes, int n_in,
                              void* d_out, int out_size) {
    const float* x  = (const float*)d_in[0];
    const float* Wq = (const float*)d_in[1];
    const float* bq = (const float*)d_in[2];
    const float* Wk = (const float*)d_in[3];
    const float* bk = (const float*)d_in[4];
    const float* Wv = (const float*)d_in[5];
    const float* bv = (const float*)d_in[6];
    const float* Wo = (const float*)d_in[7];
    const float* bo = (const float*)d_in[8];
    const float* gq = (const float*)d_in[9];
    const float* gk = (const float*)d_in[10];
    const int* seq_lens   = (const int*)d_in[11];
    const int* grid_sizes = (const int*)d_in[12];
    const float* freqs    = (const float*)d_in[13];
    float* out = (float*)d_out;

    const int L = in_sizes[0] / DIM;   // 2400

    float *pq, *pk, *pv, *pa, *pxr, *pwr;
    cudaGetSymbolAddress((void**)&pq, g_q);
    cudaGetSymbolAddress((void**)&pk, g_k);
    cudaGetSymbolAddress((void**)&pv, g_v);
    cudaGetSymbolAddress((void**)&pa, g_a);
    cudaGetSymbolAddress((void**)&pxr, g_xr);
    cudaGetSymbolAddress((void**)&pwr, g_wr);

    cudaFuncSetAttribute(gemm_qkv_kernel,
                         cudaFuncAttributeMaxDynamicSharedMemorySize, GEMM_SMEM);
    cudaFuncSetAttribute(gemm_tf32_kernel,
                         cudaFuncAttributeMaxDynamicSharedMemorySize, GEMM_SMEM);
    cudaFuncSetAttribute(attn_mma_kernel,
                         cudaFuncAttributeMaxDynamicSharedMemorySize, ASMEM);

    // --- pre-round x and weights to tf32 ---
    const int nW4 = DIM * DIM / 4;         // 589824
    const int nX4 = L * DIM / 4;
    round_tf32_kernel<<<(nX4 + 255) / 256, 256>>>(x, pxr, nX4);
    round_tf32_kernel<<<(nW4 + 255) / 256, 256>>>(Wq, pwr + 0 * (size_t)DIM * DIM, nW4);
    round_tf32_kernel<<<(nW4 + 255) / 256, 256>>>(Wk, pwr + 1 * (size_t)DIM * DIM, nW4);
    round_tf32_kernel<<<(nW4 + 255) / 256, 256>>>(Wv, pwr + 2 * (size_t)DIM * DIM, nW4);
    round_tf32_kernel<<<(nW4 + 255) / 256, 256>>>(Wo, pwr + 3 * (size_t)DIM * DIM, nW4);

    // --- fused QKV projection (rounds outputs) ---
    dim3 gq3(DIM / 128, (L + 127) / 128, 3);
    gemm_qkv_kernel<<<gq3, 256, GEMM_SMEM>>>(pxr, pwr, bq, bk, bv,
                                             pq, pk, pv, L);

    norm_rope_kernel<<<L, 256>>>(pq, pk, gq, gk, freqs, grid_sizes);

    dim3 ga((L + AQT - 1) / AQT, NH);
    attn_mma_kernel<<<ga, 128, ASMEM>>>(pq, pk, pv, pa, seq_lens, L);

    dim3 gg(DIM / 128, (L + 127) / 128);
    gemm_tf32_kernel<<<gg, 256, GEMM_SMEM>>>(pa, pwr + 3 * (size_t)DIM * DIM,
                                             bo, out, L, DIM, DIM);
}